// round 5
// baseline (speedup 1.0000x reference)
#include <cuda_runtime.h>
#include <cuda_fp16.h>

#define S      128
#define SS     16384
#define P      882
#define AK     21
#define HP     148
#define K      1681
#define LK     41
#define MR     19
#define NITERS 5
#define PW     180          // padded field width (20 left, enough right + shift)
#define PH     168          // padded field height (20 top, 20 bottom)
#define NCH    246          // uint4 weight chunks per pixel: 41 rows * 6 chunks
#define OUT_XT 32769

// ---- scratch (device globals; .bss zero-initialized; borders stay 0) ----
__device__ float g_aff [SS];
__device__ float g_lat [SS];                // field entering sre conv
__device__ float g_tmp [SS];                // field after inhibition+relu*1.5
__device__ float g_latp4 [4][PH * PW];      // conv output, 4 column-shifted copies
__device__ float g_meanp4[4][PH * PW];      // mean-sum, 4 column-shifted copies
__device__ float g_part[SS];
__device__ uint4 g_wn[(long)SS * NCH];      // fp16 normalized weights (64.5 MB)

__device__ __forceinline__ int refl(int i) {
    i = (i < 0) ? -i : i;
    return (i > 127) ? (254 - i) : i;
}

// deterministic block reduction, blockDim.x == 256
__device__ __forceinline__ float reduce1(float a) {
    __shared__ float sa[8];
    int lane = threadIdx.x & 31, w = threadIdx.x >> 5;
    #pragma unroll
    for (int o = 16; o > 0; o >>= 1) a += __shfl_down_sync(0xffffffffu, a, o);
    if (lane == 0) sa[w] = a;
    __syncthreads();
    if (w == 0) {
        a = (lane < 8) ? sa[lane] : 0.f;
        #pragma unroll
        for (int o = 4; o > 0; o >>= 1) a += __shfl_down_sync(0xffffffffu, a, o);
    }
    return a;
}

__device__ __forceinline__ void reduce2(float& a, float& b) {
    __shared__ float sa[8], sb[8];
    int lane = threadIdx.x & 31, w = threadIdx.x >> 5;
    #pragma unroll
    for (int o = 16; o > 0; o >>= 1) {
        a += __shfl_down_sync(0xffffffffu, a, o);
        b += __shfl_down_sync(0xffffffffu, b, o);
    }
    if (lane == 0) { sa[w] = a; sb[w] = b; }
    __syncthreads();
    if (w == 0) {
        a = (lane < 8) ? sa[lane] : 0.f;
        b = (lane < 8) ? sb[lane] : 0.f;
        #pragma unroll
        for (int o = 4; o > 0; o >>= 1) {
            a += __shfl_down_sync(0xffffffffu, a, o);
            b += __shfl_down_sync(0xffffffffu, b, o);
        }
    }
}

// 8-weight x 8-field MAC for one uint4 chunk
__device__ __forceinline__ float chunk_mac(uint4 wv, const float* rowp) {
    const float4* r4 = (const float4*)rowp;
    float4 f0 = r4[0], f1 = r4[1];
    float2 a = __half22float2(*(__half2*)&wv.x);
    float2 b = __half22float2(*(__half2*)&wv.y);
    float2 c = __half22float2(*(__half2*)&wv.z);
    float2 d = __half22float2(*(__half2*)&wv.w);
    return a.x * f0.x + a.y * f0.y + b.x * f0.z + b.y * f0.w
         + c.x * f1.x + c.y * f1.y + d.x * f1.z + d.y * f1.w;
}

// ---------------------------------------------------------------------------
// kA: x_tiles + raw_aff (+ in-pass rfs normalization) + per-launch init
// ---------------------------------------------------------------------------
__global__ void kA(const float* __restrict__ x, const float* __restrict__ rfs,
                   const float* __restrict__ adath, const float* __restrict__ aenv,
                   float* __restrict__ out) {
    int l = blockIdx.x;
    int y = l >> 7, c0 = l & 127;
    const float* w  = rfs + (long)l * P;
    float*       xt = out + OUT_XT + (long)l * P;
    float d1 = 0.f, d2 = 0.f;
    for (int p = threadIdx.x; p < P; p += 256) {
        int ch = (p >= 441);
        int q  = p - ch * 441;
        int di = q / AK, dj = q - di * AK;
        float xv = x[ch * (HP * HP) + (y + di) * HP + (c0 + dj)];
        float t  = xv * aenv[p];
        xt[p] = t;
        float wv = w[p];
        d1 += t * wv;
        d2 += wv;
    }
    reduce2(d1, d2);
    if (threadIdx.x == 0) {
        float inv = 1.f / d2;
        float raw = (float)P * d1 * inv;
        out[l]    = raw;
        float a   = d1 * inv - adath[l];
        g_aff[l]  = a;
        g_lat[l]  = fmaxf(a, 0.f);
        #pragma unroll
        for (int s = 0; s < 4; s++)   // reset mean field for graph replay
            g_meanp4[s][(y + 20) * PW + c0 + 20 + ((4 - s) & 3)] = 0.f;
    }
}

// ---------------------------------------------------------------------------
// kW: fold env & row-normalization into fp16 weights, uint4-chunk layout
// chunk t: di = t/6, cols 8*(t%6) .. +7 (rows padded 41 -> 48)
// ws[k] = K * w[k] * env[k] / rowsum(w)
// ---------------------------------------------------------------------------
__global__ void kW(const float* __restrict__ latw, const float* __restrict__ lenv) {
    __shared__ float sw[K];
    __shared__ float sinv;
    int l = blockIdx.x;
    const float* w = latw + (long)l * K;
    float s = 0.f;
    for (int k = threadIdx.x; k < K; k += 256) {
        float v = w[k];
        sw[k] = v;
        s += v;
    }
    s = reduce1(s);
    if (threadIdx.x == 0) sinv = (float)K / s;
    __syncthreads();
    float inv = sinv;
    int t = threadIdx.x;
    if (t < NCH) {
        int di = t / 6, c8 = (t - di * 6) * 8;
        float v[8];
        #pragma unroll
        for (int j = 0; j < 8; j++) {
            int dj = c8 + j;
            int k  = di * LK + dj;
            v[j] = (dj < LK) ? sw[k] * lenv[k] * inv : 0.f;
        }
        __half2 h0 = __floats2half2_rn(v[0], v[1]);
        __half2 h1 = __floats2half2_rn(v[2], v[3]);
        __half2 h2 = __floats2half2_rn(v[4], v[5]);
        __half2 h3 = __floats2half2_rn(v[6], v[7]);
        uint4 o;
        o.x = *(unsigned*)&h0; o.y = *(unsigned*)&h1;
        o.z = *(unsigned*)&h2; o.w = *(unsigned*)&h3;
        g_wn[(long)l * NCH + t] = o;
    }
}

// ---------------------------------------------------------------------------
// kB: 9x9 sre conv, reflect pad, smem-tiled; writes 4 shifted padded copies
// ---------------------------------------------------------------------------
__global__ void kB(const float* __restrict__ sre) {
    __shared__ float sk[81];
    __shared__ float tile[24][25];
    if (threadIdx.x < 81) sk[threadIdx.x] = sre[threadIdx.x];
    int bx = blockIdx.x * 16, by = blockIdx.y * 16;
    for (int idx = threadIdx.x; idx < 576; idx += 256) {
        int r = idx / 24, c = idx - r * 24;
        tile[r][c] = g_lat[(refl(by + r - 4) << 7) + refl(bx + c - 4)];
    }
    __syncthreads();
    int tx = threadIdx.x & 15, ty = threadIdx.x >> 4;
    float acc = 0.f;
    #pragma unroll
    for (int i = 0; i < 9; i++)
        #pragma unroll
        for (int j = 0; j < 9; j++)
            acc += tile[ty + i][tx + j] * sk[i * 9 + j];
    int base = (by + ty + 20) * PW + (bx + tx + 20);
    #pragma unroll
    for (int s = 0; s < 4; s++)
        g_latp4[s][base + ((4 - s) & 3)] = acc;
}

// ---------------------------------------------------------------------------
// kC: lateral inhibition; one uint4 chunk per thread, all 128-bit loads
// ---------------------------------------------------------------------------
__global__ void kC() {
    int l = blockIdx.x;
    int y = l >> 7, x = l & 127;
    int s = x & 3;
    int t = threadIdx.x;
    float acc = 0.f;
    if (t < NCH) {
        int di = t / 6, c8 = (t - di * 6) * 8;
        uint4 wv = g_wn[(long)l * NCH + t];
        acc = chunk_mac(wv, &g_latp4[s][(y + di) * PW + x + c8 + ((4 - s) & 3)]);
    }
    acc = reduce1(acc);
    if (t == 0) {
        float latc = g_latp4[0][(y + 20) * PW + x + 20];
        g_tmp[l] = fmaxf(latc - acc * (1.f / (float)K) + g_aff[l], 0.f) * 1.5f;
    }
}

// ---------------------------------------------------------------------------
// kD: masked 19x19 max-pool (reflect), smem-tiled with circle row-extents
// ---------------------------------------------------------------------------
__global__ void kD() {
    __shared__ float tile[34][35];
    int bx = blockIdx.x * 16, by = blockIdx.y * 16;
    for (int idx = threadIdx.x; idx < 34 * 34; idx += 256) {
        int r = idx / 34, c = idx - r * 34;
        tile[r][c] = g_tmp[(refl(by + r - 9) << 7) + refl(bx + c - 9)];
    }
    __syncthreads();
    int tx = threadIdx.x & 15, ty = threadIdx.x >> 4;
    float m = 1.0f;
    #pragma unroll
    for (int i = 0; i < MR; i++) {
        int rdi = i - 9;
        int e = (int)sqrtf(90.25f - (float)(rdi * rdi));
        const float* row = &tile[ty + i][tx + 9];
        for (int j = -e; j <= e; j++) m = fmaxf(m, row[j]);
    }
    float v = tile[ty + 9][tx + 9] / (m + 1e-5f);
    int y = by + ty, x = bx + tx;
    g_lat[(y << 7) + x] = v;
    int base = (y + 20) * PW + (x + 20);
    #pragma unroll
    for (int s = 0; s < 4; s++)
        g_meanp4[s][base + ((4 - s) & 3)] += v;
}

// ---------------------------------------------------------------------------
// kE: final correlation partials (gather on padded mean field) + final lat out
// ---------------------------------------------------------------------------
__global__ void kE(float* __restrict__ out) {
    int l = blockIdx.x;
    int y = l >> 7, x = l & 127;
    int s = x & 3;
    int t = threadIdx.x;
    float acc = 0.f;
    if (t < NCH) {
        int di = t / 6, c8 = (t - di * 6) * 8;
        uint4 wv = g_wn[(long)l * NCH + t];
        acc = chunk_mac(wv, &g_meanp4[s][(y + di) * PW + x + c8 + ((4 - s) & 3)]);
    }
    acc = reduce1(acc);
    if (t == 0) {
        float mc = g_meanp4[0][(y + 20) * PW + x + 20];
        g_part[l] = 0.04f * mc * acc;       // (1/ITERS)^2 = 0.04
        out[SS + l] = g_lat[l];
    }
}

// ---------------------------------------------------------------------------
__global__ void kF(float* __restrict__ out) {
    __shared__ float sh[512];
    float s = 0.f;
    for (int i = threadIdx.x; i < SS; i += 512) s += g_part[i];
    sh[threadIdx.x] = s;
    __syncthreads();
    for (int o = 256; o > 0; o >>= 1) {
        if (threadIdx.x < o) sh[threadIdx.x] += sh[threadIdx.x + o];
        __syncthreads();
    }
    if (threadIdx.x == 0) out[32768] = sh[0];
}

// ---------------------------------------------------------------------------
extern "C" void kernel_launch(void* const* d_in, const int* in_sizes, int n_in,
                              void* d_out, int out_size) {
    const float* x     = (const float*)d_in[0];
    const float* rfs   = (const float*)d_in[1];
    const float* latw  = (const float*)d_in[2];
    const float* adath = (const float*)d_in[3];
    const float* aenv  = (const float*)d_in[4];
    const float* sre   = (const float*)d_in[5];
    const float* lenv  = (const float*)d_in[6];
    float* out = (float*)d_out;

    kA<<<SS, 256>>>(x, rfs, adath, aenv, out);
    kW<<<SS, 256>>>(latw, lenv);
    for (int it = 0; it < NITERS; it++) {
        kB<<<dim3(8, 8), 256>>>(sre);
        kC<<<SS, 256>>>();
        kD<<<dim3(8, 8), 256>>>();
    }
    kE<<<SS, 256>>>(out);
    kF<<<1, 512>>>(out);
}

// round 6
// speedup vs baseline: 1.0323x; 1.0323x over previous
#include <cuda_runtime.h>
#include <cuda_fp16.h>

#define S      128
#define SS     16384
#define P      882
#define AK     21
#define HP     148
#define K      1681
#define LK     41
#define MR     19
#define NITERS 5
#define PW     180          // padded field width (20 left, enough right + shift)
#define PH     168          // padded field height (20 top, 20 bottom)
#define NCH    246          // uint4 weight chunks per pixel: 41 rows * 6 chunks
#define OUT_XT 32769

// ---- scratch (device globals; .bss zero-initialized; borders stay 0) ----
__device__ float g_aff [SS];
__device__ float g_lat [SS];                // field entering sre conv
__device__ float g_tmp [SS];                // field after inhibition+relu*1.5
__device__ float g_latp4 [4][PH * PW];      // conv output, 4 column-shifted copies
__device__ float g_meanp4[4][PH * PW];      // mean-sum, 4 column-shifted copies
__device__ float g_part[SS];
__device__ uint4 g_wn[(long)SS * NCH];      // fp16 normalized weights (64.5 MB)

__device__ __forceinline__ int refl(int i) {
    i = (i < 0) ? -i : i;
    return (i > 127) ? (254 - i) : i;
}

// deterministic block reduction, blockDim.x == 256
__device__ __forceinline__ float reduce1(float a) {
    __shared__ float sa[8];
    int lane = threadIdx.x & 31, w = threadIdx.x >> 5;
    #pragma unroll
    for (int o = 16; o > 0; o >>= 1) a += __shfl_down_sync(0xffffffffu, a, o);
    if (lane == 0) sa[w] = a;
    __syncthreads();
    if (w == 0) {
        a = (lane < 8) ? sa[lane] : 0.f;
        #pragma unroll
        for (int o = 4; o > 0; o >>= 1) a += __shfl_down_sync(0xffffffffu, a, o);
    }
    return a;
}

__device__ __forceinline__ void reduce2(float& a, float& b) {
    __shared__ float sa[8], sb[8];
    int lane = threadIdx.x & 31, w = threadIdx.x >> 5;
    #pragma unroll
    for (int o = 16; o > 0; o >>= 1) {
        a += __shfl_down_sync(0xffffffffu, a, o);
        b += __shfl_down_sync(0xffffffffu, b, o);
    }
    if (lane == 0) { sa[w] = a; sb[w] = b; }
    __syncthreads();
    if (w == 0) {
        a = (lane < 8) ? sa[lane] : 0.f;
        b = (lane < 8) ? sb[lane] : 0.f;
        #pragma unroll
        for (int o = 4; o > 0; o >>= 1) {
            a += __shfl_down_sync(0xffffffffu, a, o);
            b += __shfl_down_sync(0xffffffffu, b, o);
        }
    }
}

// 8-weight x 8-field MAC for one uint4 chunk
__device__ __forceinline__ float chunk_mac(uint4 wv, const float* rowp) {
    const float4* r4 = (const float4*)rowp;
    float4 f0 = r4[0], f1 = r4[1];
    float2 a = __half22float2(*(__half2*)&wv.x);
    float2 b = __half22float2(*(__half2*)&wv.y);
    float2 c = __half22float2(*(__half2*)&wv.z);
    float2 d = __half22float2(*(__half2*)&wv.w);
    return a.x * f0.x + a.y * f0.y + b.x * f0.z + b.y * f0.w
         + c.x * f1.x + c.y * f1.y + d.x * f1.z + d.y * f1.w;
}

// ---------------------------------------------------------------------------
// kA: x_tiles + raw_aff (+ in-pass rfs normalization) + per-launch init
// ---------------------------------------------------------------------------
__global__ void kA(const float* __restrict__ x, const float* __restrict__ rfs,
                   const float* __restrict__ adath, const float* __restrict__ aenv,
                   float* __restrict__ out) {
    int l = blockIdx.x;
    int y = l >> 7, c0 = l & 127;
    const float* w  = rfs + (long)l * P;
    float*       xt = out + OUT_XT + (long)l * P;
    float d1 = 0.f, d2 = 0.f;
    for (int p = threadIdx.x; p < P; p += 256) {
        int ch = (p >= 441);
        int q  = p - ch * 441;
        int di = q / AK, dj = q - di * AK;
        float xv = x[ch * (HP * HP) + (y + di) * HP + (c0 + dj)];
        float t  = xv * aenv[p];
        xt[p] = t;
        float wv = w[p];
        d1 += t * wv;
        d2 += wv;
    }
    reduce2(d1, d2);
    if (threadIdx.x == 0) {
        float inv = 1.f / d2;
        float raw = (float)P * d1 * inv;
        out[l]    = raw;
        float a   = d1 * inv - adath[l];
        g_aff[l]  = a;
        g_lat[l]  = fmaxf(a, 0.f);
        #pragma unroll
        for (int s = 0; s < 4; s++)   // reset mean field for graph replay
            g_meanp4[s][(y + 20) * PW + c0 + 20 + ((4 - s) & 3)] = 0.f;
    }
}

// ---------------------------------------------------------------------------
// kW: fold env & row-normalization into fp16 weights, uint4-chunk layout
// chunk t: di = t/6, cols 8*(t%6) .. +7 (rows padded 41 -> 48)
// ws[k] = K * w[k] * env[k] / rowsum(w)
// ---------------------------------------------------------------------------
__global__ void kW(const float* __restrict__ latw, const float* __restrict__ lenv) {
    __shared__ float sw[K];
    __shared__ float sinv;
    int l = blockIdx.x;
    const float* w = latw + (long)l * K;
    float s = 0.f;
    for (int k = threadIdx.x; k < K; k += 256) {
        float v = w[k];
        sw[k] = v;
        s += v;
    }
    s = reduce1(s);
    if (threadIdx.x == 0) sinv = (float)K / s;
    __syncthreads();
    float inv = sinv;
    int t = threadIdx.x;
    if (t < NCH) {
        int di = t / 6, c8 = (t - di * 6) * 8;
        float v[8];
        #pragma unroll
        for (int j = 0; j < 8; j++) {
            int dj = c8 + j;
            int k  = di * LK + dj;
            v[j] = (dj < LK) ? sw[k] * lenv[k] * inv : 0.f;
        }
        __half2 h0 = __floats2half2_rn(v[0], v[1]);
        __half2 h1 = __floats2half2_rn(v[2], v[3]);
        __half2 h2 = __floats2half2_rn(v[4], v[5]);
        __half2 h3 = __floats2half2_rn(v[6], v[7]);
        uint4 o;
        o.x = *(unsigned*)&h0; o.y = *(unsigned*)&h1;
        o.z = *(unsigned*)&h2; o.w = *(unsigned*)&h3;
        g_wn[(long)l * NCH + t] = o;
    }
}

// ---------------------------------------------------------------------------
// kB: 9x9 sre conv, reflect pad, smem-tiled; writes 4 shifted padded copies
// ---------------------------------------------------------------------------
__global__ void kB(const float* __restrict__ sre) {
    __shared__ float sk[81];
    __shared__ float tile[24][25];
    if (threadIdx.x < 81) sk[threadIdx.x] = sre[threadIdx.x];
    int bx = blockIdx.x * 16, by = blockIdx.y * 16;
    for (int idx = threadIdx.x; idx < 576; idx += 256) {
        int r = idx / 24, c = idx - r * 24;
        tile[r][c] = g_lat[(refl(by + r - 4) << 7) + refl(bx + c - 4)];
    }
    __syncthreads();
    int tx = threadIdx.x & 15, ty = threadIdx.x >> 4;
    float acc = 0.f;
    #pragma unroll
    for (int i = 0; i < 9; i++)
        #pragma unroll
        for (int j = 0; j < 9; j++)
            acc += tile[ty + i][tx + j] * sk[i * 9 + j];
    int base = (by + ty + 20) * PW + (bx + tx + 20);
    #pragma unroll
    for (int s = 0; s < 4; s++)
        g_latp4[s][base + ((4 - s) & 3)] = acc;
}

// ---------------------------------------------------------------------------
// kC: lateral inhibition; one uint4 chunk per thread, all 128-bit loads
// ---------------------------------------------------------------------------
__global__ void kC() {
    int l = blockIdx.x;
    int y = l >> 7, x = l & 127;
    int s = x & 3;
    int t = threadIdx.x;
    float acc = 0.f;
    if (t < NCH) {
        int di = t / 6, c8 = (t - di * 6) * 8;
        uint4 wv = g_wn[(long)l * NCH + t];
        acc = chunk_mac(wv, &g_latp4[s][(y + di) * PW + x + c8 + ((4 - s) & 3)]);
    }
    acc = reduce1(acc);
    if (t == 0) {
        float latc = g_latp4[0][(y + 20) * PW + x + 20];
        g_tmp[l] = fmaxf(latc - acc * (1.f / (float)K) + g_aff[l], 0.f) * 1.5f;
    }
}

// ---------------------------------------------------------------------------
// kD: masked 19x19 max-pool (reflect), smem-tiled with circle row-extents
// ---------------------------------------------------------------------------
__global__ void kD() {
    __shared__ float tile[34][35];
    int bx = blockIdx.x * 16, by = blockIdx.y * 16;
    for (int idx = threadIdx.x; idx < 34 * 34; idx += 256) {
        int r = idx / 34, c = idx - r * 34;
        tile[r][c] = g_tmp[(refl(by + r - 9) << 7) + refl(bx + c - 9)];
    }
    __syncthreads();
    int tx = threadIdx.x & 15, ty = threadIdx.x >> 4;
    float m = 1.0f;
    #pragma unroll
    for (int i = 0; i < MR; i++) {
        int rdi = i - 9;
        int e = (int)sqrtf(90.25f - (float)(rdi * rdi));
        const float* row = &tile[ty + i][tx + 9];
        for (int j = -e; j <= e; j++) m = fmaxf(m, row[j]);
    }
    float v = tile[ty + 9][tx + 9] / (m + 1e-5f);
    int y = by + ty, x = bx + tx;
    g_lat[(y << 7) + x] = v;
    int base = (y + 20) * PW + (x + 20);
    #pragma unroll
    for (int s = 0; s < 4; s++)
        g_meanp4[s][base + ((4 - s) & 3)] += v;
}

// ---------------------------------------------------------------------------
// kE: final correlation partials (gather on padded mean field) + final lat out
// ---------------------------------------------------------------------------
__global__ void kE(float* __restrict__ out) {
    int l = blockIdx.x;
    int y = l >> 7, x = l & 127;
    int s = x & 3;
    int t = threadIdx.x;
    float acc = 0.f;
    if (t < NCH) {
        int di = t / 6, c8 = (t - di * 6) * 8;
        uint4 wv = g_wn[(long)l * NCH + t];
        acc = chunk_mac(wv, &g_meanp4[s][(y + di) * PW + x + c8 + ((4 - s) & 3)]);
    }
    acc = reduce1(acc);
    if (t == 0) {
        float mc = g_meanp4[0][(y + 20) * PW + x + 20];
        g_part[l] = 0.04f * mc * acc;       // (1/ITERS)^2 = 0.04
        out[SS + l] = g_lat[l];
    }
}

// ---------------------------------------------------------------------------
__global__ void kF(float* __restrict__ out) {
    __shared__ float sh[512];
    float s = 0.f;
    for (int i = threadIdx.x; i < SS; i += 512) s += g_part[i];
    sh[threadIdx.x] = s;
    __syncthreads();
    for (int o = 256; o > 0; o >>= 1) {
        if (threadIdx.x < o) sh[threadIdx.x] += sh[threadIdx.x + o];
        __syncthreads();
    }
    if (threadIdx.x == 0) out[32768] = sh[0];
}

// ---------------------------------------------------------------------------
extern "C" void kernel_launch(void* const* d_in, const int* in_sizes, int n_in,
                              void* d_out, int out_size) {
    const float* x     = (const float*)d_in[0];
    const float* rfs   = (const float*)d_in[1];
    const float* latw  = (const float*)d_in[2];
    const float* adath = (const float*)d_in[3];
    const float* aenv  = (const float*)d_in[4];
    const float* sre   = (const float*)d_in[5];
    const float* lenv  = (const float*)d_in[6];
    float* out = (float*)d_out;

    kA<<<SS, 256>>>(x, rfs, adath, aenv, out);
    kW<<<SS, 256>>>(latw, lenv);
    for (int it = 0; it < NITERS; it++) {
        kB<<<dim3(8, 8), 256>>>(sre);
        kC<<<SS, 256>>>();
        kD<<<dim3(8, 8), 256>>>();
    }
    kE<<<SS, 256>>>(out);
    kF<<<1, 512>>>(out);
}

// round 8
// speedup vs baseline: 1.0814x; 1.0477x over previous
#include <cuda_runtime.h>
#include <cuda_fp16.h>

#define S      128
#define SS     16384
#define P      882
#define AK     21
#define HP     148
#define K      1681
#define LK     41
#define MR     19
#define NITERS 5
#define PW     180          // padded field width: 24 left pad + 128 + 28 right
#define PH     168          // padded field height: 20 top + 128 + 20 bottom
#define NCH    246          // uint4 weight chunks per pixel: 41 rows * 6 chunks
#define NPAIR  123          // 32-byte weight pairs per pixel
#define TW     60           // smem tile cols
#define OUT_XT 32769

// ---- scratch (device globals; .bss zero-initialized; borders stay 0) ----
__device__ float g_aff [SS];
__device__ float g_lat [SS];            // field entering sre conv
__device__ float g_tmp [SS];            // field after inhibition+relu*1.5
__device__ float g_latp [PH * PW];      // zero-padded conv output (fp32, 1 copy)
__device__ float g_meanp[PH * PW];      // zero-padded running mean-sum
__device__ float g_part[SS];
__device__ uint4 g_wn[(long)SS * NCH];  // fp16 normalized, pre-shifted weights

__device__ __forceinline__ int refl(int i) {
    i = (i < 0) ? -i : i;
    return (i > 127) ? (254 - i) : i;
}

// 32-byte weight-pair load with L2 retention hint (sm_103: evict_last needs v8.b32)
__device__ __forceinline__ void ldg_el2(const uint4* p, uint4& a, uint4& b) {
    asm("ld.global.nc.L2::evict_last.v8.b32 {%0,%1,%2,%3,%4,%5,%6,%7}, [%8];"
        : "=r"(a.x), "=r"(a.y), "=r"(a.z), "=r"(a.w),
          "=r"(b.x), "=r"(b.y), "=r"(b.z), "=r"(b.w) : "l"(p));
}

// deterministic block reduction, blockDim.x == 256
__device__ __forceinline__ float reduce1(float a) {
    __shared__ float sa[8];
    int lane = threadIdx.x & 31, w = threadIdx.x >> 5;
    #pragma unroll
    for (int o = 16; o > 0; o >>= 1) a += __shfl_down_sync(0xffffffffu, a, o);
    if (lane == 0) sa[w] = a;
    __syncthreads();
    if (w == 0) {
        a = (lane < 8) ? sa[lane] : 0.f;
        #pragma unroll
        for (int o = 4; o > 0; o >>= 1) a += __shfl_down_sync(0xffffffffu, a, o);
    }
    return a;
}

__device__ __forceinline__ void reduce2(float& a, float& b) {
    __shared__ float sa[8], sb[8];
    int lane = threadIdx.x & 31, w = threadIdx.x >> 5;
    #pragma unroll
    for (int o = 16; o > 0; o >>= 1) {
        a += __shfl_down_sync(0xffffffffu, a, o);
        b += __shfl_down_sync(0xffffffffu, b, o);
    }
    if (lane == 0) { sa[w] = a; sb[w] = b; }
    __syncthreads();
    if (w == 0) {
        a = (lane < 8) ? sa[lane] : 0.f;
        b = (lane < 8) ? sb[lane] : 0.f;
        #pragma unroll
        for (int o = 4; o > 0; o >>= 1) {
            a += __shfl_down_sync(0xffffffffu, a, o);
            b += __shfl_down_sync(0xffffffffu, b, o);
        }
    }
}

// 8-weight x 8-field MAC for one uint4 chunk against smem row pointer (16B-aligned)
__device__ __forceinline__ float chunk_mac(uint4 wv, const float* rowp) {
    const float4* r4 = (const float4*)rowp;
    float4 f0 = r4[0], f1 = r4[1];
    float2 a = __half22float2(*(__half2*)&wv.x);
    float2 b = __half22float2(*(__half2*)&wv.y);
    float2 c = __half22float2(*(__half2*)&wv.z);
    float2 d = __half22float2(*(__half2*)&wv.w);
    return a.x * f0.x + a.y * f0.y + b.x * f0.z + b.y * f0.w
         + c.x * f1.x + c.y * f1.y + d.x * f1.z + d.y * f1.w;
}

// ---------------------------------------------------------------------------
// kA: x_tiles + raw_aff (+ in-pass rfs normalization) + per-launch init
// ---------------------------------------------------------------------------
__global__ void kA(const float* __restrict__ x, const float* __restrict__ rfs,
                   const float* __restrict__ adath, const float* __restrict__ aenv,
                   float* __restrict__ out) {
    int l = blockIdx.x;
    int y = l >> 7, c0 = l & 127;
    const float* w  = rfs + (long)l * P;
    float*       xt = out + OUT_XT + (long)l * P;
    float d1 = 0.f, d2 = 0.f;
    for (int p = threadIdx.x; p < P; p += 256) {
        int ch = (p >= 441);
        int q  = p - ch * 441;
        int di = q / AK, dj = q - di * AK;
        float xv = x[ch * (HP * HP) + (y + di) * HP + (c0 + dj)];
        float t  = xv * aenv[p];
        xt[p] = t;
        float wv = w[p];
        d1 += t * wv;
        d2 += wv;
    }
    reduce2(d1, d2);
    if (threadIdx.x == 0) {
        float inv = 1.f / d2;
        float raw = (float)P * d1 * inv;
        out[l]    = raw;
        float a   = d1 * inv - adath[l];
        g_aff[l]  = a;
        g_lat[l]  = fmaxf(a, 0.f);
        g_meanp[(y + 20) * PW + c0 + 24] = 0.f;   // reset for graph replay
    }
}

// ---------------------------------------------------------------------------
// kW: fold env & row-normalization into fp16 weights, uint4-chunk layout with
// per-pixel column shift s = x&3: slot q = dj + s (rows of 48 slots).
// ws[dj] = K * w[dj] * env[dj] / rowsum(w)
// ---------------------------------------------------------------------------
__global__ void kW(const float* __restrict__ latw, const float* __restrict__ lenv) {
    __shared__ float sw[K];
    __shared__ float sinv;
    int l = blockIdx.x;
    int sft = l & 3;
    const float* w = latw + (long)l * K;
    float s = 0.f;
    for (int k = threadIdx.x; k < K; k += 256) {
        float v = w[k];
        sw[k] = v;
        s += v;
    }
    s = reduce1(s);
    if (threadIdx.x == 0) sinv = (float)K / s;
    __syncthreads();
    float inv = sinv;
    int t = threadIdx.x;
    if (t < NCH) {
        int di = t / 6, q8 = (t - di * 6) * 8;
        float v[8];
        #pragma unroll
        for (int j = 0; j < 8; j++) {
            int dj = q8 + j - sft;
            int k  = di * LK + dj;
            v[j] = ((unsigned)dj < (unsigned)LK) ? sw[k] * lenv[k] * inv : 0.f;
        }
        __half2 h0 = __floats2half2_rn(v[0], v[1]);
        __half2 h1 = __floats2half2_rn(v[2], v[3]);
        __half2 h2 = __floats2half2_rn(v[4], v[5]);
        __half2 h3 = __floats2half2_rn(v[6], v[7]);
        uint4 o;
        o.x = *(unsigned*)&h0; o.y = *(unsigned*)&h1;
        o.z = *(unsigned*)&h2; o.w = *(unsigned*)&h3;
        g_wn[(long)l * NCH + t] = o;
    }
}

// ---------------------------------------------------------------------------
// kB: 9x9 sre conv, reflect pad, smem-tiled; writes padded fp32 field
// ---------------------------------------------------------------------------
__global__ void kB(const float* __restrict__ sre) {
    __shared__ float sk[81];
    __shared__ float tile[24][25];
    if (threadIdx.x < 81) sk[threadIdx.x] = sre[threadIdx.x];
    int bx = blockIdx.x * 16, by = blockIdx.y * 16;
    for (int idx = threadIdx.x; idx < 576; idx += 256) {
        int r = idx / 24, c = idx - r * 24;
        tile[r][c] = g_lat[(refl(by + r - 4) << 7) + refl(bx + c - 4)];
    }
    __syncthreads();
    int tx = threadIdx.x & 15, ty = threadIdx.x >> 4;
    float acc = 0.f;
    #pragma unroll
    for (int i = 0; i < 9; i++)
        #pragma unroll
        for (int j = 0; j < 9; j++)
            acc += tile[ty + i][tx + j] * sk[i * 9 + j];
    g_latp[(by + ty + 20) * PW + (bx + tx + 24)] = acc;
}

// ---------------------------------------------------------------------------
// kC: lateral inhibition. Block = 8 pixels (one warp each, 256 threads).
// Field window (41 x 60) staged in smem; weights streamed as 32B pairs.
// ---------------------------------------------------------------------------
__global__ void kC() {
    __shared__ float4 tile4[41 * (TW / 4)];
    float* tile = (float*)tile4;
    int y  = blockIdx.x >> 4;
    int x0 = (blockIdx.x & 15) << 3;
    const float4* src = (const float4*)g_latp;
    int cb = x0 >> 2;
    for (int idx = threadIdx.x; idx < 41 * (TW / 4); idx += 256) {
        int rr = idx / (TW / 4), cc = idx - rr * (TW / 4);
        tile4[idx] = src[(y + rr) * (PW / 4) + cb + cc];
    }
    __syncthreads();
    int w = threadIdx.x >> 5, lam = threadIdx.x & 31;
    int l = (y << 7) + x0 + w;
    int wbase = ((w >> 2) << 2) + 4;
    const uint4* wp = g_wn + (long)l * NCH;
    float acc = 0.f;
    #pragma unroll
    for (int i = 0; i < 4; i++) {
        int p = i * 32 + lam;
        if (p < NPAIR) {
            uint4 w0, w1;
            ldg_el2(wp + 2 * p, w0, w1);
            int t0 = 2 * p, t1 = t0 + 1;
            int di0 = t0 / 6, m0 = t0 - di0 * 6;
            int di1 = t1 / 6, m1 = t1 - di1 * 6;
            acc += chunk_mac(w0, tile + di0 * TW + wbase + 8 * m0);
            acc += chunk_mac(w1, tile + di1 * TW + wbase + 8 * m1);
        }
    }
    #pragma unroll
    for (int o = 16; o > 0; o >>= 1) acc += __shfl_down_sync(0xffffffffu, acc, o);
    if (lam == 0) {
        float latc = tile[20 * TW + 24 + w];
        g_tmp[l] = fmaxf(latc - acc * (1.f / (float)K) + g_aff[l], 0.f) * 1.5f;
    }
}

// ---------------------------------------------------------------------------
// kD: masked 19x19 max-pool (reflect), smem-tiled; updates g_lat + padded mean
// ---------------------------------------------------------------------------
__global__ void kD() {
    __shared__ float tile[34][35];
    int bx = blockIdx.x * 16, by = blockIdx.y * 16;
    for (int idx = threadIdx.x; idx < 34 * 34; idx += 256) {
        int r = idx / 34, c = idx - r * 34;
        tile[r][c] = g_tmp[(refl(by + r - 9) << 7) + refl(bx + c - 9)];
    }
    __syncthreads();
    int tx = threadIdx.x & 15, ty = threadIdx.x >> 4;
    float m = 1.0f;
    #pragma unroll
    for (int i = 0; i < MR; i++) {
        int rdi = i - 9;
        int e = (int)sqrtf(90.25f - (float)(rdi * rdi));
        const float* row = &tile[ty + i][tx + 9];
        for (int j = -e; j <= e; j++) m = fmaxf(m, row[j]);
    }
    float v = tile[ty + 9][tx + 9] / (m + 1e-5f);
    int y = by + ty, x = bx + tx;
    g_lat[(y << 7) + x] = v;
    g_meanp[(y + 20) * PW + (x + 24)] += v;
}

// ---------------------------------------------------------------------------
// kE: final correlation partials (same structure as kC on mean field)
// ---------------------------------------------------------------------------
__global__ void kE(float* __restrict__ out) {
    __shared__ float4 tile4[41 * (TW / 4)];
    float* tile = (float*)tile4;
    int y  = blockIdx.x >> 4;
    int x0 = (blockIdx.x & 15) << 3;
    const float4* src = (const float4*)g_meanp;
    int cb = x0 >> 2;
    for (int idx = threadIdx.x; idx < 41 * (TW / 4); idx += 256) {
        int rr = idx / (TW / 4), cc = idx - rr * (TW / 4);
        tile4[idx] = src[(y + rr) * (PW / 4) + cb + cc];
    }
    __syncthreads();
    int w = threadIdx.x >> 5, lam = threadIdx.x & 31;
    int l = (y << 7) + x0 + w;
    int wbase = ((w >> 2) << 2) + 4;
    const uint4* wp = g_wn + (long)l * NCH;
    float acc = 0.f;
    #pragma unroll
    for (int i = 0; i < 4; i++) {
        int p = i * 32 + lam;
        if (p < NPAIR) {
            uint4 w0, w1;
            ldg_el2(wp + 2 * p, w0, w1);
            int t0 = 2 * p, t1 = t0 + 1;
            int di0 = t0 / 6, m0 = t0 - di0 * 6;
            int di1 = t1 / 6, m1 = t1 - di1 * 6;
            acc += chunk_mac(w0, tile + di0 * TW + wbase + 8 * m0);
            acc += chunk_mac(w1, tile + di1 * TW + wbase + 8 * m1);
        }
    }
    #pragma unroll
    for (int o = 16; o > 0; o >>= 1) acc += __shfl_down_sync(0xffffffffu, acc, o);
    if (lam == 0) {
        float mc = tile[20 * TW + 24 + w];
        g_part[l] = 0.04f * mc * acc;       // (1/ITERS)^2 = 0.04
        out[SS + l] = g_lat[l];
    }
}

// ---------------------------------------------------------------------------
__global__ void kF(float* __restrict__ out) {
    __shared__ float sh[512];
    float s = 0.f;
    for (int i = threadIdx.x; i < SS; i += 512) s += g_part[i];
    sh[threadIdx.x] = s;
    __syncthreads();
    for (int o = 256; o > 0; o >>= 1) {
        if (threadIdx.x < o) sh[threadIdx.x] += sh[threadIdx.x + o];
        __syncthreads();
    }
    if (threadIdx.x == 0) out[32768] = sh[0];
}

// ---------------------------------------------------------------------------
extern "C" void kernel_launch(void* const* d_in, const int* in_sizes, int n_in,
                              void* d_out, int out_size) {
    const float* x     = (const float*)d_in[0];
    const float* rfs   = (const float*)d_in[1];
    const float* latw  = (const float*)d_in[2];
    const float* adath = (const float*)d_in[3];
    const float* aenv  = (const float*)d_in[4];
    const float* sre   = (const float*)d_in[5];
    const float* lenv  = (const float*)d_in[6];
    float* out = (float*)d_out;

    kA<<<SS, 256>>>(x, rfs, adath, aenv, out);
    kW<<<SS, 256>>>(latw, lenv);
    for (int it = 0; it < NITERS; it++) {
        kB<<<dim3(8, 8), 256>>>(sre);
        kC<<<SS / 8, 256>>>();
        kD<<<dim3(8, 8), 256>>>();
    }
    kE<<<SS / 8, 256>>>(out);
    kF<<<1, 512>>>(out);
}

// round 10
// speedup vs baseline: 1.2273x; 1.1349x over previous
#include <cuda_runtime.h>
#include <cuda_fp16.h>

#define S      128
#define SS     16384
#define P      882
#define AK     21
#define HP     148
#define K      1681
#define LK     41
#define MR     19
#define NITERS 5
#define PW     180          // padded field width: 24 left pad + 128 + 28 right
#define PH     168          // padded field height: 20 top + 128 + 20 bottom
#define NCH    246          // uint4 chunks (8 fp16) per pixel: 41 rows * 6
#define TW     56           // smem half-tile cols (112B row stride, 16B aligned)
#define OUT_XT 32769

// ---- scratch (device globals; .bss zero-initialized; borders stay 0) ----
__device__ float g_aff [SS];
__device__ float g_lat [SS];            // field entering sre conv
__device__ float g_tmp [SS];            // field after inhibition+relu*1.5
__device__ float g_latp [PH * PW];      // zero-padded conv output (fp32)
__device__ float g_meanp[PH * PW];      // zero-padded running mean-sum
__device__ float g_part[SS];
__device__ uint4 g_wn[(long)SS * NCH];  // fp16 normalized, pre-shifted weights (64.5MB)

__device__ __forceinline__ int refl(int i) {
    i = (i < 0) ? -i : i;
    return (i > 127) ? (254 - i) : i;
}

// deterministic block reduction (blockDim.x in {256,512})
__device__ __forceinline__ float reduce1(float a) {
    __shared__ float sa[16];
    int lane = threadIdx.x & 31, w = threadIdx.x >> 5;
    int nw = blockDim.x >> 5;
    #pragma unroll
    for (int o = 16; o > 0; o >>= 1) a += __shfl_down_sync(0xffffffffu, a, o);
    if (lane == 0) sa[w] = a;
    __syncthreads();
    if (w == 0) {
        a = (lane < nw) ? sa[lane] : 0.f;
        #pragma unroll
        for (int o = 8; o > 0; o >>= 1) a += __shfl_down_sync(0xffffffffu, a, o);
    }
    return a;
}

__device__ __forceinline__ void reduce2(float& a, float& b) {
    __shared__ float sa[8], sb[8];
    int lane = threadIdx.x & 31, w = threadIdx.x >> 5;
    #pragma unroll
    for (int o = 16; o > 0; o >>= 1) {
        a += __shfl_down_sync(0xffffffffu, a, o);
        b += __shfl_down_sync(0xffffffffu, b, o);
    }
    if (lane == 0) { sa[w] = a; sb[w] = b; }
    __syncthreads();
    if (w == 0) {
        a = (lane < 8) ? sa[lane] : 0.f;
        b = (lane < 8) ? sb[lane] : 0.f;
        #pragma unroll
        for (int o = 4; o > 0; o >>= 1) {
            a += __shfl_down_sync(0xffffffffu, a, o);
            b += __shfl_down_sync(0xffffffffu, b, o);
        }
    }
}

// 8 fp16 weights (uint4) x 8 fp16 field halves (uint4), fp32 accumulate
__device__ __forceinline__ float chunk_mac(uint4 wv, uint4 fv) {
    float2 w0 = __half22float2(*(__half2*)&wv.x);
    float2 w1 = __half22float2(*(__half2*)&wv.y);
    float2 w2 = __half22float2(*(__half2*)&wv.z);
    float2 w3 = __half22float2(*(__half2*)&wv.w);
    float2 f0 = __half22float2(*(__half2*)&fv.x);
    float2 f1 = __half22float2(*(__half2*)&fv.y);
    float2 f2 = __half22float2(*(__half2*)&fv.z);
    float2 f3 = __half22float2(*(__half2*)&fv.w);
    return w0.x * f0.x + w0.y * f0.y + w1.x * f1.x + w1.y * f1.y
         + w2.x * f2.x + w2.y * f2.y + w3.x * f3.x + w3.y * f3.y;
}

// ---------------------------------------------------------------------------
// kA: x_tiles + raw_aff (+ in-pass rfs normalization) + per-launch init
// ---------------------------------------------------------------------------
__global__ void kA(const float* __restrict__ x, const float* __restrict__ rfs,
                   const float* __restrict__ adath, const float* __restrict__ aenv,
                   float* __restrict__ out) {
    int l = blockIdx.x;
    int y = l >> 7, c0 = l & 127;
    const float* w  = rfs + (long)l * P;
    float*       xt = out + OUT_XT + (long)l * P;
    float d1 = 0.f, d2 = 0.f;
    for (int p = threadIdx.x; p < P; p += 256) {
        int ch = (p >= 441);
        int q  = p - ch * 441;
        int di = q / AK, dj = q - di * AK;
        float xv = x[ch * (HP * HP) + (y + di) * HP + (c0 + dj)];
        float t  = xv * aenv[p];
        xt[p] = t;
        float wv = w[p];
        d1 += t * wv;
        d2 += wv;
    }
    reduce2(d1, d2);
    if (threadIdx.x == 0) {
        float inv = 1.f / d2;
        float raw = (float)P * d1 * inv;
        out[l]    = raw;
        float a   = d1 * inv - adath[l];
        g_aff[l]  = a;
        g_lat[l]  = fmaxf(a, 0.f);
        g_meanp[(y + 20) * PW + c0 + 24] = 0.f;   // reset for graph replay
    }
}

// ---------------------------------------------------------------------------
// kW: fold env & row-normalization into fp16 weights, uint4 chunk layout with
// per-pixel column shift sft = x&7: slot q = dj + sft (rows of 48 slots).
// ws[dj] = K * w[dj] * env[dj] / rowsum(w)
// ---------------------------------------------------------------------------
__global__ void kW(const float* __restrict__ latw, const float* __restrict__ lenv) {
    __shared__ float sw[K];
    __shared__ float sinv;
    int l = blockIdx.x;
    int sft = l & 7;
    const float* w = latw + (long)l * K;
    float s = 0.f;
    for (int k = threadIdx.x; k < K; k += 256) {
        float v = w[k];
        sw[k] = v;
        s += v;
    }
    s = reduce1(s);
    if (threadIdx.x == 0) sinv = (float)K / s;
    __syncthreads();
    float inv = sinv;
    int t = threadIdx.x;
    if (t < NCH) {
        int di = t / 6, q8 = (t - di * 6) * 8;
        float v[8];
        #pragma unroll
        for (int j = 0; j < 8; j++) {
            int dj = q8 + j - sft;
            int k  = di * LK + dj;
            v[j] = ((unsigned)dj < (unsigned)LK) ? sw[k] * lenv[k] * inv : 0.f;
        }
        __half2 h0 = __floats2half2_rn(v[0], v[1]);
        __half2 h1 = __floats2half2_rn(v[2], v[3]);
        __half2 h2 = __floats2half2_rn(v[4], v[5]);
        __half2 h3 = __floats2half2_rn(v[6], v[7]);
        uint4 o;
        o.x = *(unsigned*)&h0; o.y = *(unsigned*)&h1;
        o.z = *(unsigned*)&h2; o.w = *(unsigned*)&h3;
        g_wn[(long)l * NCH + t] = o;
    }
}

// ---------------------------------------------------------------------------
// kB: 9x9 sre conv, reflect pad, smem-tiled; writes padded fp32 field
// ---------------------------------------------------------------------------
__global__ void kB(const float* __restrict__ sre) {
    __shared__ float sk[81];
    __shared__ float tile[24][25];
    if (threadIdx.x < 81) sk[threadIdx.x] = sre[threadIdx.x];
    int bx = blockIdx.x * 16, by = blockIdx.y * 16;
    for (int idx = threadIdx.x; idx < 576; idx += 256) {
        int r = idx / 24, c = idx - r * 24;
        tile[r][c] = g_lat[(refl(by + r - 4) << 7) + refl(bx + c - 4)];
    }
    __syncthreads();
    int tx = threadIdx.x & 15, ty = threadIdx.x >> 4;
    float acc = 0.f;
    #pragma unroll
    for (int i = 0; i < 9; i++)
        #pragma unroll
        for (int j = 0; j < 9; j++)
            acc += tile[ty + i][tx + j] * sk[i * 9 + j];
    g_latp[(by + ty + 20) * PW + (bx + tx + 24)] = acc;
}

// ---------------------------------------------------------------------------
// kC: lateral inhibition. Block = 16 pixels (one warp each, 512 threads).
// Field window (41 x 56) staged in smem as fp16; fp16 weights streamed.
// Pixel w slot q -> tile half (w>>3)*8 + q = w + dj (16B-aligned per chunk).
// ---------------------------------------------------------------------------
__global__ void kC() {
    __shared__ __align__(16) __half tile[41 * TW];
    int y  = blockIdx.x >> 3;
    int x0 = (blockIdx.x & 7) << 4;
    const float4* src = (const float4*)g_latp;
    int cb = (x0 + 4) >> 2;                 // tile origin = padded col x0+4
    for (int idx = threadIdx.x; idx < 41 * (TW / 4); idx += 512) {
        int rr = idx / (TW / 4), cc = idx - rr * (TW / 4);
        float4 f = src[(y + rr) * (PW / 4) + cb + cc];
        __half2* dst = (__half2*)(tile + rr * TW + cc * 4);
        dst[0] = __floats2half2_rn(f.x, f.y);
        dst[1] = __floats2half2_rn(f.z, f.w);
    }
    __syncthreads();
    int w = threadIdx.x >> 5, lam = threadIdx.x & 31;
    int l = (y << 7) + x0 + w;
    const uint4* wp = g_wn + (long)l * NCH;
    const uint4* tb = (const uint4*)(tile + ((w >> 3) << 3));
    float acc = 0.f;
    #pragma unroll
    for (int i = 0; i < 8; i++) {
        int t = i * 32 + lam;
        if (t < NCH) {
            uint4 wv = __ldg(wp + t);
            int di = t / 6, m = t - di * 6;
            acc += chunk_mac(wv, tb[di * (TW / 8) + m]);
        }
    }
    #pragma unroll
    for (int o = 16; o > 0; o >>= 1) acc += __shfl_down_sync(0xffffffffu, acc, o);
    if (lam == 0) {
        float latc = g_latp[(y + 20) * PW + x0 + w + 24];
        g_tmp[l] = fmaxf(latc - acc * (1.f / (float)K) + g_aff[l], 0.f) * 1.5f;
    }
}

// ---------------------------------------------------------------------------
// kD: masked 19x19 max-pool (reflect), smem-tiled; updates g_lat + padded mean
// ---------------------------------------------------------------------------
__global__ void kD() {
    __shared__ float tile[34][35];
    int bx = blockIdx.x * 16, by = blockIdx.y * 16;
    for (int idx = threadIdx.x; idx < 34 * 34; idx += 256) {
        int r = idx / 34, c = idx - r * 34;
        tile[r][c] = g_tmp[(refl(by + r - 9) << 7) + refl(bx + c - 9)];
    }
    __syncthreads();
    int tx = threadIdx.x & 15, ty = threadIdx.x >> 4;
    float m = 1.0f;
    #pragma unroll
    for (int i = 0; i < MR; i++) {
        int rdi = i - 9;
        int e = (int)sqrtf(90.25f - (float)(rdi * rdi));
        const float* row = &tile[ty + i][tx + 9];
        for (int j = -e; j <= e; j++) m = fmaxf(m, row[j]);
    }
    float v = tile[ty + 9][tx + 9] / (m + 1e-5f);
    int y = by + ty, x = bx + tx;
    g_lat[(y << 7) + x] = v;
    g_meanp[(y + 20) * PW + (x + 24)] += v;
}

// ---------------------------------------------------------------------------
// kE: final correlation partials (same structure as kC on mean field)
// ---------------------------------------------------------------------------
__global__ void kE(float* __restrict__ out) {
    __shared__ __align__(16) __half tile[41 * TW];
    int y  = blockIdx.x >> 3;
    int x0 = (blockIdx.x & 7) << 4;
    const float4* src = (const float4*)g_meanp;
    int cb = (x0 + 4) >> 2;
    for (int idx = threadIdx.x; idx < 41 * (TW / 4); idx += 512) {
        int rr = idx / (TW / 4), cc = idx - rr * (TW / 4);
        float4 f = src[(y + rr) * (PW / 4) + cb + cc];
        __half2* dst = (__half2*)(tile + rr * TW + cc * 4);
        dst[0] = __floats2half2_rn(f.x, f.y);
        dst[1] = __floats2half2_rn(f.z, f.w);
    }
    __syncthreads();
    int w = threadIdx.x >> 5, lam = threadIdx.x & 31;
    int l = (y << 7) + x0 + w;
    const uint4* wp = g_wn + (long)l * NCH;
    const uint4* tb = (const uint4*)(tile + ((w >> 3) << 3));
    float acc = 0.f;
    #pragma unroll
    for (int i = 0; i < 8; i++) {
        int t = i * 32 + lam;
        if (t < NCH) {
            uint4 wv = __ldg(wp + t);
            int di = t / 6, m = t - di * 6;
            acc += chunk_mac(wv, tb[di * (TW / 8) + m]);
        }
    }
    #pragma unroll
    for (int o = 16; o > 0; o >>= 1) acc += __shfl_down_sync(0xffffffffu, acc, o);
    if (lam == 0) {
        float mc = g_meanp[(y + 20) * PW + x0 + w + 24];
        g_part[l] = 0.04f * mc * acc;       // (1/ITERS)^2 = 0.04
        out[SS + l] = g_lat[l];
    }
}

// ---------------------------------------------------------------------------
__global__ void kF(float* __restrict__ out) {
    __shared__ float sh[512];
    float s = 0.f;
    for (int i = threadIdx.x; i < SS; i += 512) s += g_part[i];
    sh[threadIdx.x] = s;
    __syncthreads();
    for (int o = 256; o > 0; o >>= 1) {
        if (threadIdx.x < o) sh[threadIdx.x] += sh[threadIdx.x + o];
        __syncthreads();
    }
    if (threadIdx.x == 0) out[32768] = sh[0];
}

// ---------------------------------------------------------------------------
extern "C" void kernel_launch(void* const* d_in, const int* in_sizes, int n_in,
                              void* d_out, int out_size) {
    const float* x     = (const float*)d_in[0];
    const float* rfs   = (const float*)d_in[1];
    const float* latw  = (const float*)d_in[2];
    const float* adath = (const float*)d_in[3];
    const float* aenv  = (const float*)d_in[4];
    const float* sre   = (const float*)d_in[5];
    const float* lenv  = (const float*)d_in[6];
    float* out = (float*)d_out;

    kA<<<SS, 256>>>(x, rfs, adath, aenv, out);
    kW<<<SS, 256>>>(latw, lenv);
    for (int it = 0; it < NITERS; it++) {
        kB<<<dim3(8, 8), 256>>>(sre);
        kC<<<SS / 16, 512>>>();
        kD<<<dim3(8, 8), 256>>>();
    }
    kE<<<SS / 16, 512>>>(out);
    kF<<<1, 512>>>(out);
}

// round 11
// speedup vs baseline: 1.2368x; 1.0078x over previous
#include <cuda_runtime.h>
#include <cuda_fp16.h>

#define S      128
#define SS     16384
#define P      882
#define AK     21
#define HP     148
#define K      1681
#define LK     41
#define MR     19
#define NITERS 5
#define PW     180          // padded field width: 24 left pad + 128 + 28 right
#define PH     168          // padded field height: 20 top + 128 + 20 bottom
#define NCH    246          // uint4 chunks (8 fp16) per pixel: 41 rows * 6
#define NPAIR  123          // 32B chunk-pairs per pixel
#define TW     56           // smem half-tile cols
#define OUT_XT 32769
#define NBLK   512          // kC/kE persistent blocks (single wave)

// ---- scratch (device globals; .bss zero-initialized; borders stay 0) ----
__device__ float g_aff [SS];
__device__ float g_lat [SS];
__device__ float g_tmp [SS];
__device__ float g_latp [PH * PW];
__device__ float g_meanp[PH * PW];
__device__ float g_part[SS];
__device__ __align__(32) uint4 g_wn[(long)SS * NCH];  // fp16 weights (64.5MB)

__device__ __forceinline__ int refl(int i) {
    i = (i < 0) ? -i : i;
    return (i > 127) ? (254 - i) : i;
}

// 32-byte weight-pair load (sm_103 256-bit load, L2 retention hint)
__device__ __forceinline__ void ldg_w2(const uint4* p, uint4& a, uint4& b) {
    asm("ld.global.nc.L2::evict_last.v8.b32 {%0,%1,%2,%3,%4,%5,%6,%7}, [%8];"
        : "=r"(a.x), "=r"(a.y), "=r"(a.z), "=r"(a.w),
          "=r"(b.x), "=r"(b.y), "=r"(b.z), "=r"(b.w) : "l"(p));
}

// deterministic block reduction (blockDim.x == 256)
__device__ __forceinline__ float reduce1(float a) {
    __shared__ float sa[8];
    int lane = threadIdx.x & 31, w = threadIdx.x >> 5;
    #pragma unroll
    for (int o = 16; o > 0; o >>= 1) a += __shfl_down_sync(0xffffffffu, a, o);
    if (lane == 0) sa[w] = a;
    __syncthreads();
    if (w == 0) {
        a = (lane < 8) ? sa[lane] : 0.f;
        #pragma unroll
        for (int o = 4; o > 0; o >>= 1) a += __shfl_down_sync(0xffffffffu, a, o);
    }
    return a;
}

__device__ __forceinline__ void reduce2(float& a, float& b) {
    __shared__ float sa[8], sb[8];
    int lane = threadIdx.x & 31, w = threadIdx.x >> 5;
    #pragma unroll
    for (int o = 16; o > 0; o >>= 1) {
        a += __shfl_down_sync(0xffffffffu, a, o);
        b += __shfl_down_sync(0xffffffffu, b, o);
    }
    if (lane == 0) { sa[w] = a; sb[w] = b; }
    __syncthreads();
    if (w == 0) {
        a = (lane < 8) ? sa[lane] : 0.f;
        b = (lane < 8) ? sb[lane] : 0.f;
        #pragma unroll
        for (int o = 4; o > 0; o >>= 1) {
            a += __shfl_down_sync(0xffffffffu, a, o);
            b += __shfl_down_sync(0xffffffffu, b, o);
        }
    }
}

// 8 fp16 weights (uint4) x 8 fp16 field halves (uint4), fp32 accumulate
__device__ __forceinline__ float chunk_mac(uint4 wv, uint4 fv) {
    float2 w0 = __half22float2(*(__half2*)&wv.x);
    float2 w1 = __half22float2(*(__half2*)&wv.y);
    float2 w2 = __half22float2(*(__half2*)&wv.z);
    float2 w3 = __half22float2(*(__half2*)&wv.w);
    float2 f0 = __half22float2(*(__half2*)&fv.x);
    float2 f1 = __half22float2(*(__half2*)&fv.y);
    float2 f2 = __half22float2(*(__half2*)&fv.z);
    float2 f3 = __half22float2(*(__half2*)&fv.w);
    return w0.x * f0.x + w0.y * f0.y + w1.x * f1.x + w1.y * f1.y
         + w2.x * f2.x + w2.y * f2.y + w3.x * f3.x + w3.y * f3.y;
}

// ---------------------------------------------------------------------------
// kAW: fused afferent pass (even blocks) + weight conversion (odd blocks).
// Two independent DRAM streams interleaved across all SMs.
// ---------------------------------------------------------------------------
__global__ void kAW(const float* __restrict__ x, const float* __restrict__ rfs,
                    const float* __restrict__ adath, const float* __restrict__ aenv,
                    const float* __restrict__ latw, const float* __restrict__ lenv,
                    float* __restrict__ out) {
    __shared__ float sw[K];
    __shared__ float sinv;
    int l = blockIdx.x >> 1;
    if ((blockIdx.x & 1) == 0) {
        // ---- kA: x_tiles + raw_aff + init ----
        int y = l >> 7, c0 = l & 127;
        const float* w  = rfs + (long)l * P;
        float*       xt = out + OUT_XT + (long)l * P;
        float d1 = 0.f, d2 = 0.f;
        for (int p = threadIdx.x; p < P; p += 256) {
            int ch = (p >= 441);
            int q  = p - ch * 441;
            int di = q / AK, dj = q - di * AK;
            float xv = x[ch * (HP * HP) + (y + di) * HP + (c0 + dj)];
            float t  = xv * aenv[p];
            xt[p] = t;
            float wv = w[p];
            d1 += t * wv;
            d2 += wv;
        }
        reduce2(d1, d2);
        if (threadIdx.x == 0) {
            float inv = 1.f / d2;
            float raw = (float)P * d1 * inv;
            out[l]    = raw;
            float a   = d1 * inv - adath[l];
            g_aff[l]  = a;
            g_lat[l]  = fmaxf(a, 0.f);
            g_meanp[(y + 20) * PW + c0 + 24] = 0.f;   // reset for graph replay
        }
    } else {
        // ---- kW: normalized fp16 weights, pre-shifted (sft = x&7) ----
        int sft = l & 7;
        const float* w = latw + (long)l * K;
        float s = 0.f;
        for (int k = threadIdx.x; k < K; k += 256) {
            float v = w[k];
            sw[k] = v;
            s += v;
        }
        s = reduce1(s);
        if (threadIdx.x == 0) sinv = (float)K / s;
        __syncthreads();
        float inv = sinv;
        int t = threadIdx.x;
        if (t < NCH) {
            int di = t / 6, q8 = (t - di * 6) * 8;
            float v[8];
            #pragma unroll
            for (int j = 0; j < 8; j++) {
                int dj = q8 + j - sft;
                int k  = di * LK + dj;
                v[j] = ((unsigned)dj < (unsigned)LK) ? sw[k] * lenv[k] * inv : 0.f;
            }
            __half2 h0 = __floats2half2_rn(v[0], v[1]);
            __half2 h1 = __floats2half2_rn(v[2], v[3]);
            __half2 h2 = __floats2half2_rn(v[4], v[5]);
            __half2 h3 = __floats2half2_rn(v[6], v[7]);
            uint4 o;
            o.x = *(unsigned*)&h0; o.y = *(unsigned*)&h1;
            o.z = *(unsigned*)&h2; o.w = *(unsigned*)&h3;
            g_wn[(long)l * NCH + t] = o;
        }
    }
}

// ---------------------------------------------------------------------------
// kB: 9x9 sre conv, reflect pad, smem-tiled; writes padded fp32 field
// ---------------------------------------------------------------------------
__global__ void kB(const float* __restrict__ sre) {
    __shared__ float sk[81];
    __shared__ float tile[24][25];
    if (threadIdx.x < 81) sk[threadIdx.x] = sre[threadIdx.x];
    int bx = blockIdx.x * 16, by = blockIdx.y * 16;
    for (int idx = threadIdx.x; idx < 576; idx += 256) {
        int r = idx / 24, c = idx - r * 24;
        tile[r][c] = g_lat[(refl(by + r - 4) << 7) + refl(bx + c - 4)];
    }
    __syncthreads();
    int tx = threadIdx.x & 15, ty = threadIdx.x >> 4;
    float acc = 0.f;
    #pragma unroll
    for (int i = 0; i < 9; i++)
        #pragma unroll
        for (int j = 0; j < 9; j++)
            acc += tile[ty + i][tx + j] * sk[i * 9 + j];
    g_latp[(by + ty + 20) * PW + (bx + tx + 24)] = acc;
}

// ---------------------------------------------------------------------------
// kC: lateral inhibition. 512 persistent blocks (single wave), 2 tiles each.
// Tile = 16 pixels (one warp each); field window fp16 in smem; 32B weight pairs.
// ---------------------------------------------------------------------------
__global__ void kC() {
    __shared__ __align__(16) __half tile[41 * TW];
    int w = threadIdx.x >> 5, lam = threadIdx.x & 31;
    #pragma unroll
    for (int rep = 0; rep < 2; rep++) {
        int tl = blockIdx.x + rep * NBLK;
        int y  = tl >> 3;
        int x0 = (tl & 7) << 4;
        __syncthreads();                         // previous tile fully consumed
        const float4* src = (const float4*)g_latp;
        int cb = (x0 + 4) >> 2;
        for (int idx = threadIdx.x; idx < 41 * (TW / 4); idx += 512) {
            int rr = idx / (TW / 4), cc = idx - rr * (TW / 4);
            float4 f = src[(y + rr) * (PW / 4) + cb + cc];
            __half2* dst = (__half2*)(tile + rr * TW + cc * 4);
            dst[0] = __floats2half2_rn(f.x, f.y);
            dst[1] = __floats2half2_rn(f.z, f.w);
        }
        __syncthreads();
        int l = (y << 7) + x0 + w;
        const uint4* wp = g_wn + (long)l * NCH;
        const uint4* tb = (const uint4*)(tile + ((w >> 3) << 3));
        float acc = 0.f;
        #pragma unroll
        for (int i = 0; i < 4; i++) {
            int p = i * 32 + lam;
            if (p < NPAIR) {
                uint4 w0, w1;
                ldg_w2(wp + 2 * p, w0, w1);
                int q = p / 3, r = p - 3 * q;    // chunks 6q+2r, 6q+2r+1 (same row)
                int base = q * (TW / 8) + 2 * r;
                acc += chunk_mac(w0, tb[base]);
                acc += chunk_mac(w1, tb[base + 1]);
            }
        }
        #pragma unroll
        for (int o = 16; o > 0; o >>= 1) acc += __shfl_down_sync(0xffffffffu, acc, o);
        if (lam == 0) {
            float latc = g_latp[(y + 20) * PW + x0 + w + 24];
            g_tmp[l] = fmaxf(latc - acc * (1.f / (float)K) + g_aff[l], 0.f) * 1.5f;
        }
    }
}

// ---------------------------------------------------------------------------
// kD: masked 19x19 max-pool (reflect), smem-tiled; updates g_lat + padded mean
// ---------------------------------------------------------------------------
__global__ void kD() {
    __shared__ float tile[34][35];
    int bx = blockIdx.x * 16, by = blockIdx.y * 16;
    for (int idx = threadIdx.x; idx < 34 * 34; idx += 256) {
        int r = idx / 34, c = idx - r * 34;
        tile[r][c] = g_tmp[(refl(by + r - 9) << 7) + refl(bx + c - 9)];
    }
    __syncthreads();
    int tx = threadIdx.x & 15, ty = threadIdx.x >> 4;
    float m = 1.0f;
    #pragma unroll
    for (int i = 0; i < MR; i++) {
        int rdi = i - 9;
        int e = (int)sqrtf(90.25f - (float)(rdi * rdi));
        const float* row = &tile[ty + i][tx + 9];
        for (int j = -e; j <= e; j++) m = fmaxf(m, row[j]);
    }
    float v = tile[ty + 9][tx + 9] / (m + 1e-5f);
    int y = by + ty, x = bx + tx;
    g_lat[(y << 7) + x] = v;
    g_meanp[(y + 20) * PW + (x + 24)] += v;
}

// ---------------------------------------------------------------------------
// kE: final correlation partials (same structure as kC on mean field)
// ---------------------------------------------------------------------------
__global__ void kE(float* __restrict__ out) {
    __shared__ __align__(16) __half tile[41 * TW];
    int w = threadIdx.x >> 5, lam = threadIdx.x & 31;
    #pragma unroll
    for (int rep = 0; rep < 2; rep++) {
        int tl = blockIdx.x + rep * NBLK;
        int y  = tl >> 3;
        int x0 = (tl & 7) << 4;
        __syncthreads();
        const float4* src = (const float4*)g_meanp;
        int cb = (x0 + 4) >> 2;
        for (int idx = threadIdx.x; idx < 41 * (TW / 4); idx += 512) {
            int rr = idx / (TW / 4), cc = idx - rr * (TW / 4);
            float4 f = src[(y + rr) * (PW / 4) + cb + cc];
            __half2* dst = (__half2*)(tile + rr * TW + cc * 4);
            dst[0] = __floats2half2_rn(f.x, f.y);
            dst[1] = __floats2half2_rn(f.z, f.w);
        }
        __syncthreads();
        int l = (y << 7) + x0 + w;
        const uint4* wp = g_wn + (long)l * NCH;
        const uint4* tb = (const uint4*)(tile + ((w >> 3) << 3));
        float acc = 0.f;
        #pragma unroll
        for (int i = 0; i < 4; i++) {
            int p = i * 32 + lam;
            if (p < NPAIR) {
                uint4 w0, w1;
                ldg_w2(wp + 2 * p, w0, w1);
                int q = p / 3, r = p - 3 * q;
                int base = q * (TW / 8) + 2 * r;
                acc += chunk_mac(w0, tb[base]);
                acc += chunk_mac(w1, tb[base + 1]);
            }
        }
        #pragma unroll
        for (int o = 16; o > 0; o >>= 1) acc += __shfl_down_sync(0xffffffffu, acc, o);
        if (lam == 0) {
            float mc = g_meanp[(y + 20) * PW + x0 + w + 24];
            g_part[l] = 0.04f * mc * acc;       // (1/ITERS)^2 = 0.04
            out[SS + l] = g_lat[l];
        }
    }
}

// ---------------------------------------------------------------------------
__global__ void kF(float* __restrict__ out) {
    __shared__ float sh[512];
    float s = 0.f;
    for (int i = threadIdx.x; i < SS; i += 512) s += g_part[i];
    sh[threadIdx.x] = s;
    __syncthreads();
    for (int o = 256; o > 0; o >>= 1) {
        if (threadIdx.x < o) sh[threadIdx.x] += sh[threadIdx.x + o];
        __syncthreads();
    }
    if (threadIdx.x == 0) out[32768] = sh[0];
}

// ---------------------------------------------------------------------------
extern "C" void kernel_launch(void* const* d_in, const int* in_sizes, int n_in,
                              void* d_out, int out_size) {
    const float* x     = (const float*)d_in[0];
    const float* rfs   = (const float*)d_in[1];
    const float* latw  = (const float*)d_in[2];
    const float* adath = (const float*)d_in[3];
    const float* aenv  = (const float*)d_in[4];
    const float* sre   = (const float*)d_in[5];
    const float* lenv  = (const float*)d_in[6];
    float* out = (float*)d_out;

    kAW<<<2 * SS, 256>>>(x, rfs, adath, aenv, latw, lenv, out);
    for (int it = 0; it < NITERS; it++) {
        kB<<<dim3(8, 8), 256>>>(sre);
        kC<<<NBLK, 512>>>();
        kD<<<dim3(8, 8), 256>>>();
    }
    kE<<<NBLK, 512>>>(out);
    kF<<<1, 512>>>(out);
}

// round 12
// speedup vs baseline: 1.2670x; 1.0244x over previous
#include <cuda_runtime.h>
#include <cuda_fp16.h>

#define S      128
#define SS     16384
#define P      882
#define AK     21
#define HP     148
#define K      1681
#define LK     41
#define MR     19
#define NITERS 5
#define PW     180          // padded field width: 24 left pad + 128 + 28 right
#define PH     168          // padded field height: 20 top + 128 + 20 bottom
#define NCH    246          // uint4 chunks (8 fp16) per pixel: 41 rows * 6
#define NPAIR  123          // 32B chunk-pairs per pixel
#define TW     56           // smem half-tile cols
#define OUT_XT 32769
#define NBLK   512          // kC/kE persistent blocks (single wave)

// ---- scratch (device globals; .bss zero-initialized; borders stay 0) ----
__device__ float g_aff [SS];
__device__ float g_lat [SS];
__device__ float g_tmp [SS];
__device__ float g_latp [PH * PW];
__device__ float g_meanp[PH * PW];
__device__ float g_part[SS];
__device__ __align__(32) uint4 g_wn[(long)SS * NCH];  // fp16 weights (64.5MB)

__device__ __forceinline__ int refl(int i) {
    i = (i < 0) ? -i : i;
    return (i > 127) ? (254 - i) : i;
}

// 32-byte weight-pair load (sm_103 256-bit load, L2 retention hint)
__device__ __forceinline__ void ldg_w2(const uint4* p, uint4& a, uint4& b) {
    asm("ld.global.nc.L2::evict_last.v8.b32 {%0,%1,%2,%3,%4,%5,%6,%7}, [%8];"
        : "=r"(a.x), "=r"(a.y), "=r"(a.z), "=r"(a.w),
          "=r"(b.x), "=r"(b.y), "=r"(b.z), "=r"(b.w) : "l"(p));
}

// deterministic block reduction (blockDim.x == 256)
__device__ __forceinline__ float reduce1(float a) {
    __shared__ float sa[8];
    int lane = threadIdx.x & 31, w = threadIdx.x >> 5;
    #pragma unroll
    for (int o = 16; o > 0; o >>= 1) a += __shfl_down_sync(0xffffffffu, a, o);
    if (lane == 0) sa[w] = a;
    __syncthreads();
    if (w == 0) {
        a = (lane < 8) ? sa[lane] : 0.f;
        #pragma unroll
        for (int o = 4; o > 0; o >>= 1) a += __shfl_down_sync(0xffffffffu, a, o);
    }
    return a;
}

__device__ __forceinline__ void reduce2(float& a, float& b) {
    __shared__ float sa[8], sb[8];
    int lane = threadIdx.x & 31, w = threadIdx.x >> 5;
    #pragma unroll
    for (int o = 16; o > 0; o >>= 1) {
        a += __shfl_down_sync(0xffffffffu, a, o);
        b += __shfl_down_sync(0xffffffffu, b, o);
    }
    if (lane == 0) { sa[w] = a; sb[w] = b; }
    __syncthreads();
    if (w == 0) {
        a = (lane < 8) ? sa[lane] : 0.f;
        b = (lane < 8) ? sb[lane] : 0.f;
        #pragma unroll
        for (int o = 4; o > 0; o >>= 1) {
            a += __shfl_down_sync(0xffffffffu, a, o);
            b += __shfl_down_sync(0xffffffffu, b, o);
        }
    }
}

// 8 fp16 weights (uint4) x 8 fp16 field halves (uint4), fp32 accumulate
__device__ __forceinline__ float chunk_mac(uint4 wv, uint4 fv) {
    float2 w0 = __half22float2(*(__half2*)&wv.x);
    float2 w1 = __half22float2(*(__half2*)&wv.y);
    float2 w2 = __half22float2(*(__half2*)&wv.z);
    float2 w3 = __half22float2(*(__half2*)&wv.w);
    float2 f0 = __half22float2(*(__half2*)&fv.x);
    float2 f1 = __half22float2(*(__half2*)&fv.y);
    float2 f2 = __half22float2(*(__half2*)&fv.z);
    float2 f3 = __half22float2(*(__half2*)&fv.w);
    return w0.x * f0.x + w0.y * f0.y + w1.x * f1.x + w1.y * f1.y
         + w2.x * f2.x + w2.y * f2.y + w3.x * f3.x + w3.y * f3.y;
}

// ---------------------------------------------------------------------------
// kAW: fused afferent pass (even blocks) + weight conversion (odd blocks).
// ---------------------------------------------------------------------------
__global__ void kAW(const float* __restrict__ x, const float* __restrict__ rfs,
                    const float* __restrict__ adath, const float* __restrict__ aenv,
                    const float* __restrict__ latw, const float* __restrict__ lenv,
                    float* __restrict__ out) {
    __shared__ float sw[K];
    __shared__ float sinv;
    int l = blockIdx.x >> 1;
    if ((blockIdx.x & 1) == 0) {
        // ---- kA: x_tiles + raw_aff + init ----
        int y = l >> 7, c0 = l & 127;
        const float* w  = rfs + (long)l * P;
        float*       xt = out + OUT_XT + (long)l * P;
        float d1 = 0.f, d2 = 0.f;
        for (int p = threadIdx.x; p < P; p += 256) {
            int ch = (p >= 441);
            int q  = p - ch * 441;
            int di = q / AK, dj = q - di * AK;
            float xv = x[ch * (HP * HP) + (y + di) * HP + (c0 + dj)];
            float t  = xv * aenv[p];
            xt[p] = t;
            float wv = w[p];
            d1 += t * wv;
            d2 += wv;
        }
        reduce2(d1, d2);
        if (threadIdx.x == 0) {
            float inv = 1.f / d2;
            float raw = (float)P * d1 * inv;
            out[l]    = raw;
            float a   = d1 * inv - adath[l];
            g_aff[l]  = a;
            g_lat[l]  = fmaxf(a, 0.f);
            g_meanp[(y + 20) * PW + c0 + 24] = 0.f;   // reset for graph replay
        }
    } else {
        // ---- kW: normalized fp16 weights, pre-shifted (sft = x&7) ----
        int sft = l & 7;
        const float* w = latw + (long)l * K;
        float s = 0.f;
        for (int k = threadIdx.x; k < K; k += 256) {
            float v = w[k];
            sw[k] = v;
            s += v;
        }
        s = reduce1(s);
        if (threadIdx.x == 0) sinv = (float)K / s;
        __syncthreads();
        float inv = sinv;
        int t = threadIdx.x;
        if (t < NCH) {
            int di = t / 6, q8 = (t - di * 6) * 8;
            float v[8];
            #pragma unroll
            for (int j = 0; j < 8; j++) {
                int dj = q8 + j - sft;
                int k  = di * LK + dj;
                v[j] = ((unsigned)dj < (unsigned)LK) ? sw[k] * lenv[k] * inv : 0.f;
            }
            __half2 h0 = __floats2half2_rn(v[0], v[1]);
            __half2 h1 = __floats2half2_rn(v[2], v[3]);
            __half2 h2 = __floats2half2_rn(v[4], v[5]);
            __half2 h3 = __floats2half2_rn(v[6], v[7]);
            uint4 o;
            o.x = *(unsigned*)&h0; o.y = *(unsigned*)&h1;
            o.z = *(unsigned*)&h2; o.w = *(unsigned*)&h3;
            g_wn[(long)l * NCH + t] = o;
        }
    }
}

// ---------------------------------------------------------------------------
// kB: 9x9 sre conv, reflect pad, smem-tiled. 16x8 tiles -> 128 blocks.
// ---------------------------------------------------------------------------
__global__ void kB(const float* __restrict__ sre) {
    __shared__ float sk[81];
    __shared__ float tile[16][25];
    if (threadIdx.x < 81) sk[threadIdx.x] = sre[threadIdx.x];
    int bx = blockIdx.x * 16, by = blockIdx.y * 8;
    for (int idx = threadIdx.x; idx < 16 * 24; idx += 128) {
        int r = idx / 24, c = idx - r * 24;
        tile[r][c] = g_lat[(refl(by + r - 4) << 7) + refl(bx + c - 4)];
    }
    __syncthreads();
    int tx = threadIdx.x & 15, ty = threadIdx.x >> 4;
    float acc = 0.f;
    #pragma unroll
    for (int i = 0; i < 9; i++)
        #pragma unroll
        for (int j = 0; j < 9; j++)
            acc += tile[ty + i][tx + j] * sk[i * 9 + j];
    g_latp[(by + ty + 20) * PW + (bx + tx + 24)] = acc;
}

// ---------------------------------------------------------------------------
// kC: lateral inhibition. 512 persistent blocks (single wave), 2 tiles each.
// ---------------------------------------------------------------------------
__global__ void kC() {
    __shared__ __align__(16) __half tile[41 * TW];
    int w = threadIdx.x >> 5, lam = threadIdx.x & 31;
    #pragma unroll
    for (int rep = 0; rep < 2; rep++) {
        int tl = blockIdx.x + rep * NBLK;
        int y  = tl >> 3;
        int x0 = (tl & 7) << 4;
        __syncthreads();
        const float4* src = (const float4*)g_latp;
        int cb = (x0 + 4) >> 2;
        for (int idx = threadIdx.x; idx < 41 * (TW / 4); idx += 512) {
            int rr = idx / (TW / 4), cc = idx - rr * (TW / 4);
            float4 f = src[(y + rr) * (PW / 4) + cb + cc];
            __half2* dst = (__half2*)(tile + rr * TW + cc * 4);
            dst[0] = __floats2half2_rn(f.x, f.y);
            dst[1] = __floats2half2_rn(f.z, f.w);
        }
        __syncthreads();
        int l = (y << 7) + x0 + w;
        const uint4* wp = g_wn + (long)l * NCH;
        const uint4* tb = (const uint4*)(tile + ((w >> 3) << 3));
        float acc = 0.f;
        #pragma unroll
        for (int i = 0; i < 4; i++) {
            int p = i * 32 + lam;
            if (p < NPAIR) {
                uint4 w0, w1;
                ldg_w2(wp + 2 * p, w0, w1);
                int q = p / 3, r = p - 3 * q;
                int base = q * (TW / 8) + 2 * r;
                acc += chunk_mac(w0, tb[base]);
                acc += chunk_mac(w1, tb[base + 1]);
            }
        }
        #pragma unroll
        for (int o = 16; o > 0; o >>= 1) acc += __shfl_down_sync(0xffffffffu, acc, o);
        if (lam == 0) {
            float latc = g_latp[(y + 20) * PW + x0 + w + 24];
            g_tmp[l] = fmaxf(latc - acc * (1.f / (float)K) + g_aff[l], 0.f) * 1.5f;
        }
    }
}

// ---------------------------------------------------------------------------
// kD: masked 19x19 max-pool. 16x8 tiles, 4 threads/pixel -> 128 blocks x 512.
// ---------------------------------------------------------------------------
__global__ void kD() {
    __shared__ float tile[26][35];
    int bx = blockIdx.x * 16, by = blockIdx.y * 8;
    for (int idx = threadIdx.x; idx < 26 * 34; idx += 512) {
        int r = idx / 34, c = idx - r * 34;
        tile[r][c] = g_tmp[(refl(by + r - 9) << 7) + refl(bx + c - 9)];
    }
    __syncthreads();
    int j  = threadIdx.x & 3;          // row-group within pixel
    int p  = threadIdx.x >> 2;         // pixel 0..127
    int px = p & 15, py = p >> 4;
    float m = 1.0f;
    for (int i = j; i < MR; i += 4) {
        int rdi = i - 9;
        int e = (int)sqrtf(90.25f - (float)(rdi * rdi));
        const float* row = &tile[py + i][px + 9];
        for (int jj = -e; jj <= e; jj++) m = fmaxf(m, row[jj]);
    }
    m = fmaxf(m, __shfl_xor_sync(0xffffffffu, m, 1));
    m = fmaxf(m, __shfl_xor_sync(0xffffffffu, m, 2));
    if (j == 0) {
        float v = tile[py + 9][px + 9] / (m + 1e-5f);
        int y = by + py, x = bx + px;
        g_lat[(y << 7) + x] = v;
        g_meanp[(y + 20) * PW + (x + 24)] += v;
    }
}

// ---------------------------------------------------------------------------
// kE: final correlation partials (same structure as kC on mean field)
// ---------------------------------------------------------------------------
__global__ void kE(float* __restrict__ out) {
    __shared__ __align__(16) __half tile[41 * TW];
    int w = threadIdx.x >> 5, lam = threadIdx.x & 31;
    #pragma unroll
    for (int rep = 0; rep < 2; rep++) {
        int tl = blockIdx.x + rep * NBLK;
        int y  = tl >> 3;
        int x0 = (tl & 7) << 4;
        __syncthreads();
        const float4* src = (const float4*)g_meanp;
        int cb = (x0 + 4) >> 2;
        for (int idx = threadIdx.x; idx < 41 * (TW / 4); idx += 512) {
            int rr = idx / (TW / 4), cc = idx - rr * (TW / 4);
            float4 f = src[(y + rr) * (PW / 4) + cb + cc];
            __half2* dst = (__half2*)(tile + rr * TW + cc * 4);
            dst[0] = __floats2half2_rn(f.x, f.y);
            dst[1] = __floats2half2_rn(f.z, f.w);
        }
        __syncthreads();
        int l = (y << 7) + x0 + w;
        const uint4* wp = g_wn + (long)l * NCH;
        const uint4* tb = (const uint4*)(tile + ((w >> 3) << 3));
        float acc = 0.f;
        #pragma unroll
        for (int i = 0; i < 4; i++) {
            int p = i * 32 + lam;
            if (p < NPAIR) {
                uint4 w0, w1;
                ldg_w2(wp + 2 * p, w0, w1);
                int q = p / 3, r = p - 3 * q;
                int base = q * (TW / 8) + 2 * r;
                acc += chunk_mac(w0, tb[base]);
                acc += chunk_mac(w1, tb[base + 1]);
            }
        }
        #pragma unroll
        for (int o = 16; o > 0; o >>= 1) acc += __shfl_down_sync(0xffffffffu, acc, o);
        if (lam == 0) {
            float mc = g_meanp[(y + 20) * PW + x0 + w + 24];
            g_part[l] = 0.04f * mc * acc;       // (1/ITERS)^2 = 0.04
            out[SS + l] = g_lat[l];
        }
    }
}

// ---------------------------------------------------------------------------
__global__ void kF(float* __restrict__ out) {
    __shared__ float sh[512];
    float s = 0.f;
    for (int i = threadIdx.x; i < SS; i += 512) s += g_part[i];
    sh[threadIdx.x] = s;
    __syncthreads();
    for (int o = 256; o > 0; o >>= 1) {
        if (threadIdx.x < o) sh[threadIdx.x] += sh[threadIdx.x + o];
        __syncthreads();
    }
    if (threadIdx.x == 0) out[32768] = sh[0];
}

// ---------------------------------------------------------------------------
extern "C" void kernel_launch(void* const* d_in, const int* in_sizes, int n_in,
                              void* d_out, int out_size) {
    const float* x     = (const float*)d_in[0];
    const float* rfs   = (const float*)d_in[1];
    const float* latw  = (const float*)d_in[2];
    const float* adath = (const float*)d_in[3];
    const float* aenv  = (const float*)d_in[4];
    const float* sre   = (const float*)d_in[5];
    const float* lenv  = (const float*)d_in[6];
    float* out = (float*)d_out;

    kAW<<<2 * SS, 256>>>(x, rfs, adath, aenv, latw, lenv, out);
    for (int it = 0; it < NITERS; it++) {
        kB<<<dim3(8, 16), 128>>>(sre);
        kC<<<NBLK, 512>>>();
        kD<<<dim3(8, 16), 512>>>();
    }
    kE<<<NBLK, 512>>>(out);
    kF<<<1, 512>>>(out);
}

// round 13
// speedup vs baseline: 1.2731x; 1.0048x over previous
#include <cuda_runtime.h>
#include <cuda_fp16.h>

#define S      128
#define SS     16384
#define P      882
#define AK     21
#define HP     148
#define K      1681
#define LK     41
#define MR     19
#define NITERS 5
#define PW     180          // padded field width: 24 left pad + 128 + 28 right
#define PH     168          // padded field height: 20 top + 128 + 20 bottom
#define NCH    246          // uint4 chunks (8 fp16) per pixel: 41 rows * 6
#define NPAIR  123          // 32B chunk-pairs per pixel
#define TW     56           // smem half-tile cols
#define OUT_XT 32769
#define NBLK   512          // kC/kE persistent blocks (single wave)

// ---- scratch (device globals; .bss zero-initialized; borders stay 0) ----
__device__ float g_aff [SS];
__device__ float g_lat [SS];
__device__ float g_tmp [SS];
__device__ float g_latp [PH * PW];
__device__ float g_meanp[PH * PW];
__device__ float g_part[SS];
__device__ __align__(32) uint4 g_wn[(long)SS * NCH];  // fp16 weights (64.5MB)

__device__ __forceinline__ int refl(int i) {
    i = (i < 0) ? -i : i;
    return (i > 127) ? (254 - i) : i;
}

// 32-byte weight-pair load (sm_103 256-bit load, L2 retention hint)
__device__ __forceinline__ void ldg_w2(const uint4* p, uint4& a, uint4& b) {
    asm("ld.global.nc.L2::evict_last.v8.b32 {%0,%1,%2,%3,%4,%5,%6,%7}, [%8];"
        : "=r"(a.x), "=r"(a.y), "=r"(a.z), "=r"(a.w),
          "=r"(b.x), "=r"(b.y), "=r"(b.z), "=r"(b.w) : "l"(p));
}

// deterministic block reduction (blockDim.x == 256)
__device__ __forceinline__ float reduce1(float a) {
    __shared__ float sa[8];
    int lane = threadIdx.x & 31, w = threadIdx.x >> 5;
    #pragma unroll
    for (int o = 16; o > 0; o >>= 1) a += __shfl_down_sync(0xffffffffu, a, o);
    if (lane == 0) sa[w] = a;
    __syncthreads();
    if (w == 0) {
        a = (lane < 8) ? sa[lane] : 0.f;
        #pragma unroll
        for (int o = 4; o > 0; o >>= 1) a += __shfl_down_sync(0xffffffffu, a, o);
    }
    return a;
}

__device__ __forceinline__ void reduce2(float& a, float& b) {
    __shared__ float sa[8], sb[8];
    int lane = threadIdx.x & 31, w = threadIdx.x >> 5;
    #pragma unroll
    for (int o = 16; o > 0; o >>= 1) {
        a += __shfl_down_sync(0xffffffffu, a, o);
        b += __shfl_down_sync(0xffffffffu, b, o);
    }
    if (lane == 0) { sa[w] = a; sb[w] = b; }
    __syncthreads();
    if (w == 0) {
        a = (lane < 8) ? sa[lane] : 0.f;
        b = (lane < 8) ? sb[lane] : 0.f;
        #pragma unroll
        for (int o = 4; o > 0; o >>= 1) {
            a += __shfl_down_sync(0xffffffffu, a, o);
            b += __shfl_down_sync(0xffffffffu, b, o);
        }
    }
}

// 8 fp16 weights (uint4) x 8 fp16 field halves (uint4), fp32 accumulate
__device__ __forceinline__ float chunk_mac(uint4 wv, uint4 fv) {
    float2 w0 = __half22float2(*(__half2*)&wv.x);
    float2 w1 = __half22float2(*(__half2*)&wv.y);
    float2 w2 = __half22float2(*(__half2*)&wv.z);
    float2 w3 = __half22float2(*(__half2*)&wv.w);
    float2 f0 = __half22float2(*(__half2*)&fv.x);
    float2 f1 = __half22float2(*(__half2*)&fv.y);
    float2 f2 = __half22float2(*(__half2*)&fv.z);
    float2 f3 = __half22float2(*(__half2*)&fv.w);
    return w0.x * f0.x + w0.y * f0.y + w1.x * f1.x + w1.y * f1.y
         + w2.x * f2.x + w2.y * f2.y + w3.x * f3.x + w3.y * f3.y;
}

// ---------------------------------------------------------------------------
// kAW: fused afferent pass (even blocks) + weight conversion (odd blocks).
// ---------------------------------------------------------------------------
__global__ void kAW(const float* __restrict__ x, const float* __restrict__ rfs,
                    const float* __restrict__ adath, const float* __restrict__ aenv,
                    const float* __restrict__ latw, const float* __restrict__ lenv,
                    float* __restrict__ out) {
    __shared__ float sw[K];
    __shared__ float sinv;
    int l = blockIdx.x >> 1;
    if ((blockIdx.x & 1) == 0) {
        // ---- kA: x_tiles + raw_aff + init ----
        int y = l >> 7, c0 = l & 127;
        const float* w  = rfs + (long)l * P;
        float*       xt = out + OUT_XT + (long)l * P;
        float d1 = 0.f, d2 = 0.f;
        for (int p = threadIdx.x; p < P; p += 256) {
            int ch = (p >= 441);
            int q  = p - ch * 441;
            int di = q / AK, dj = q - di * AK;
            float xv = x[ch * (HP * HP) + (y + di) * HP + (c0 + dj)];
            float t  = xv * aenv[p];
            xt[p] = t;
            float wv = w[p];
            d1 += t * wv;
            d2 += wv;
        }
        reduce2(d1, d2);
        if (threadIdx.x == 0) {
            float inv = 1.f / d2;
            float raw = (float)P * d1 * inv;
            out[l]    = raw;
            float a   = d1 * inv - adath[l];
            g_aff[l]  = a;
            g_lat[l]  = fmaxf(a, 0.f);
            g_meanp[(y + 20) * PW + c0 + 24] = 0.f;   // reset for graph replay
        }
    } else {
        // ---- kW: normalized fp16 weights, pre-shifted (sft = x&7) ----
        int sft = l & 7;
        const float* w = latw + (long)l * K;
        float s = 0.f;
        for (int k = threadIdx.x; k < K; k += 256) {
            float v = w[k];
            sw[k] = v;
            s += v;
        }
        s = reduce1(s);
        if (threadIdx.x == 0) sinv = (float)K / s;
        __syncthreads();
        float inv = sinv;
        int t = threadIdx.x;
        if (t < NCH) {
            int di = t / 6, q8 = (t - di * 6) * 8;
            float v[8];
            #pragma unroll
            for (int j = 0; j < 8; j++) {
                int dj = q8 + j - sft;
                int k  = di * LK + dj;
                v[j] = ((unsigned)dj < (unsigned)LK) ? sw[k] * lenv[k] * inv : 0.f;
            }
            __half2 h0 = __floats2half2_rn(v[0], v[1]);
            __half2 h1 = __floats2half2_rn(v[2], v[3]);
            __half2 h2 = __floats2half2_rn(v[4], v[5]);
            __half2 h3 = __floats2half2_rn(v[6], v[7]);
            uint4 o;
            o.x = *(unsigned*)&h0; o.y = *(unsigned*)&h1;
            o.z = *(unsigned*)&h2; o.w = *(unsigned*)&h3;
            g_wn[(long)l * NCH + t] = o;
        }
    }
}

// ---------------------------------------------------------------------------
// kB: 9x9 sre conv, reflect pad, smem-tiled. 16x8 tiles -> 128 blocks.
// ---------------------------------------------------------------------------
__global__ void kB(const float* __restrict__ sre) {
    __shared__ float sk[81];
    __shared__ float tile[16][25];
    if (threadIdx.x < 81) sk[threadIdx.x] = sre[threadIdx.x];
    int bx = blockIdx.x * 16, by = blockIdx.y * 8;
    for (int idx = threadIdx.x; idx < 16 * 24; idx += 128) {
        int r = idx / 24, c = idx - r * 24;
        tile[r][c] = g_lat[(refl(by + r - 4) << 7) + refl(bx + c - 4)];
    }
    __syncthreads();
    int tx = threadIdx.x & 15, ty = threadIdx.x >> 4;
    float acc = 0.f;
    #pragma unroll
    for (int i = 0; i < 9; i++)
        #pragma unroll
        for (int j = 0; j < 9; j++)
            acc += tile[ty + i][tx + j] * sk[i * 9 + j];
    g_latp[(by + ty + 20) * PW + (bx + tx + 24)] = acc;
}

// ---------------------------------------------------------------------------
// kC: lateral inhibition. 512 persistent blocks (single wave), 2 tiles each.
// ---------------------------------------------------------------------------
__global__ void kC() {
    __shared__ __align__(16) __half tile[41 * TW];
    int w = threadIdx.x >> 5, lam = threadIdx.x & 31;
    #pragma unroll
    for (int rep = 0; rep < 2; rep++) {
        int tl = blockIdx.x + rep * NBLK;
        int y  = tl >> 3;
        int x0 = (tl & 7) << 4;
        __syncthreads();
        const float4* src = (const float4*)g_latp;
        int cb = (x0 + 4) >> 2;
        for (int idx = threadIdx.x; idx < 41 * (TW / 4); idx += 512) {
            int rr = idx / (TW / 4), cc = idx - rr * (TW / 4);
            float4 f = src[(y + rr) * (PW / 4) + cb + cc];
            __half2* dst = (__half2*)(tile + rr * TW + cc * 4);
            dst[0] = __floats2half2_rn(f.x, f.y);
            dst[1] = __floats2half2_rn(f.z, f.w);
        }
        __syncthreads();
        int l = (y << 7) + x0 + w;
        const uint4* wp = g_wn + (long)l * NCH;
        const uint4* tb = (const uint4*)(tile + ((w >> 3) << 3));
        float acc = 0.f;
        #pragma unroll
        for (int i = 0; i < 4; i++) {
            int p = i * 32 + lam;
            if (p < NPAIR) {
                uint4 w0, w1;
                ldg_w2(wp + 2 * p, w0, w1);
                int q = p / 3, r = p - 3 * q;
                int base = q * (TW / 8) + 2 * r;
                acc += chunk_mac(w0, tb[base]);
                acc += chunk_mac(w1, tb[base + 1]);
            }
        }
        #pragma unroll
        for (int o = 16; o > 0; o >>= 1) acc += __shfl_down_sync(0xffffffffu, acc, o);
        if (lam == 0) {
            float latc = g_latp[(y + 20) * PW + x0 + w + 24];
            g_tmp[l] = fmaxf(latc - acc * (1.f / (float)K) + g_aff[l], 0.f) * 1.5f;
        }
    }
}

// ---------------------------------------------------------------------------
// kD: masked 19x19 max-pool. 16x8 tiles, 4 threads/pixel -> 128 blocks x 512.
// ---------------------------------------------------------------------------
__global__ void kD() {
    __shared__ float tile[26][35];
    int bx = blockIdx.x * 16, by = blockIdx.y * 8;
    for (int idx = threadIdx.x; idx < 26 * 34; idx += 512) {
        int r = idx / 34, c = idx - r * 34;
        tile[r][c] = g_tmp[(refl(by + r - 9) << 7) + refl(bx + c - 9)];
    }
    __syncthreads();
    int j  = threadIdx.x & 3;          // row-group within pixel
    int p  = threadIdx.x >> 2;         // pixel 0..127
    int px = p & 15, py = p >> 4;
    float m = 1.0f;
    for (int i = j; i < MR; i += 4) {
        int rdi = i - 9;
        int e = (int)sqrtf(90.25f - (float)(rdi * rdi));
        const float* row = &tile[py + i][px + 9];
        for (int jj = -e; jj <= e; jj++) m = fmaxf(m, row[jj]);
    }
    m = fmaxf(m, __shfl_xor_sync(0xffffffffu, m, 1));
    m = fmaxf(m, __shfl_xor_sync(0xffffffffu, m, 2));
    if (j == 0) {
        float v = tile[py + 9][px + 9] / (m + 1e-5f);
        int y = by + py, x = bx + px;
        g_lat[(y << 7) + x] = v;
        g_meanp[(y + 20) * PW + (x + 24)] += v;
    }
}

// ---------------------------------------------------------------------------
// kE: final correlation partials (same structure as kC on mean field)
// ---------------------------------------------------------------------------
__global__ void kE(float* __restrict__ out) {
    __shared__ __align__(16) __half tile[41 * TW];
    int w = threadIdx.x >> 5, lam = threadIdx.x & 31;
    #pragma unroll
    for (int rep = 0; rep < 2; rep++) {
        int tl = blockIdx.x + rep * NBLK;
        int y  = tl >> 3;
        int x0 = (tl & 7) << 4;
        __syncthreads();
        const float4* src = (const float4*)g_meanp;
        int cb = (x0 + 4) >> 2;
        for (int idx = threadIdx.x; idx < 41 * (TW / 4); idx += 512) {
            int rr = idx / (TW / 4), cc = idx - rr * (TW / 4);
            float4 f = src[(y + rr) * (PW / 4) + cb + cc];
            __half2* dst = (__half2*)(tile + rr * TW + cc * 4);
            dst[0] = __floats2half2_rn(f.x, f.y);
            dst[1] = __floats2half2_rn(f.z, f.w);
        }
        __syncthreads();
        int l = (y << 7) + x0 + w;
        const uint4* wp = g_wn + (long)l * NCH;
        const uint4* tb = (const uint4*)(tile + ((w >> 3) << 3));
        float acc = 0.f;
        #pragma unroll
        for (int i = 0; i < 4; i++) {
            int p = i * 32 + lam;
            if (p < NPAIR) {
                uint4 w0, w1;
                ldg_w2(wp + 2 * p, w0, w1);
                int q = p / 3, r = p - 3 * q;
                int base = q * (TW / 8) + 2 * r;
                acc += chunk_mac(w0, tb[base]);
                acc += chunk_mac(w1, tb[base + 1]);
            }
        }
        #pragma unroll
        for (int o = 16; o > 0; o >>= 1) acc += __shfl_down_sync(0xffffffffu, acc, o);
        if (lam == 0) {
            float mc = g_meanp[(y + 20) * PW + x0 + w + 24];
            g_part[l] = 0.04f * mc * acc;       // (1/ITERS)^2 = 0.04
            out[SS + l] = g_lat[l];
        }
    }
}

// ---------------------------------------------------------------------------
__global__ void kF(float* __restrict__ out) {
    __shared__ float sh[512];
    float s = 0.f;
    for (int i = threadIdx.x; i < SS; i += 512) s += g_part[i];
    sh[threadIdx.x] = s;
    __syncthreads();
    for (int o = 256; o > 0; o >>= 1) {
        if (threadIdx.x < o) sh[threadIdx.x] += sh[threadIdx.x + o];
        __syncthreads();
    }
    if (threadIdx.x == 0) out[32768] = sh[0];
}

// ---------------------------------------------------------------------------
extern "C" void kernel_launch(void* const* d_in, const int* in_sizes, int n_in,
                              void* d_out, int out_size) {
    const float* x     = (const float*)d_in[0];
    const float* rfs   = (const float*)d_in[1];
    const float* latw  = (const float*)d_in[2];
    const float* adath = (const float*)d_in[3];
    const float* aenv  = (const float*)d_in[4];
    const float* sre   = (const float*)d_in[5];
    const float* lenv  = (const float*)d_in[6];
    float* out = (float*)d_out;

    kAW<<<2 * SS, 256>>>(x, rfs, adath, aenv, latw, lenv, out);
    for (int it = 0; it < NITERS; it++) {
        kB<<<dim3(8, 16), 128>>>(sre);
        kC<<<NBLK, 512>>>();
        kD<<<dim3(8, 16), 512>>>();
    }
    kE<<<NBLK, 512>>>(out);
    kF<<<1, 512>>>(out);
}